// round 5
// baseline (speedup 1.0000x reference)
#include <cuda_runtime.h>

// Fused: channel-mix (w1) -> double-unfold 1D conv along W (w0, torch-style
// two-stage zero-pad masks) -> roll(+1) along H.
//
// x  : [128, 56, 56] f32, w0 : [32,2,3,3], w1 : [4,64], out : [128,56,56]
//
// out[l*4+p, o, n] = sum_{j,i,k} w0[l,j,i,k] * t4[p,j,(o-1)%56, n+i+k-2]
//                    * [0 <= n+k-1 < 56] * [0 <= n+i+k-2 < 56]
// t4[p,j,h,w] = sum_c w1[p,c] * x[2c+j, h, w]
//
// Combined weights per (l,j), grouped by d=i+k:
//   r0=w(0,0) [t4(n-2), n>=2]   r1=w(0,1)+w(1,0) [t4(n-1), n>=1]
//   r2=w(1,1) [t4(n)]           r3=w(2,0) [t4(n), n>=1]
//   r4=w(0,2) [t4(n), n<=54]    r5=w(1,2)+w(2,1) [t4(n+1), n<=54]
//   r6=w(2,2) [t4(n+2), n<=53]
// Center terms fold: wc = r2+r3+r4 everywhere except n=0 (drop r3) and
// n=55 (drop r4) -> 5-tap kernel + two scalar fixups.
//
// Grid: 112 CTAs = 56 rows x 2 W-halves (halo 2 on t4). Block: 256.

#define NT 256

__global__ __launch_bounds__(NT, 1) void fused_shuffleconv2(
    const float* __restrict__ x,
    const float* __restrict__ w0,
    const float* __restrict__ w1,
    float* __restrict__ out)
{
    __shared__ float xs[128 * 36];   // x row slice, cols [wbase-4, wbase+32), stride 36
    __shared__ float t4s[8 * 33];    // t4 rows (p*2+j), local idx m <-> global col wbase-2+m
    __shared__ float w1s[256];
    __shared__ float wcs[32 * 16];   // combined weights [l][j*7+r], padded to 16

    const int tid   = threadIdx.x;
    const int o     = blockIdx.x >> 1;
    const int wbase = (blockIdx.x & 1) * 28;
    const int hsrc  = (o + 55) % 56;          // roll(+1): out row o <- y row o-1

    // ---- prologue ----
    w1s[tid] = w1[tid];

    #pragma unroll
    for (int e = tid; e < 448; e += NT) {     // 32 l * 14 combined weights
        int l = e / 14, q = e % 14;
        int j = q / 7,  r = q % 7;
        const float* wb = w0 + (l * 2 + j) * 9;   // [3][3], idx = i*3+k
        float v;
        switch (r) {
            case 0:  v = wb[0];          break;
            case 1:  v = wb[1] + wb[3];  break;
            case 2:  v = wb[4];          break;
            case 3:  v = wb[6];          break;
            case 4:  v = wb[2];          break;
            case 5:  v = wb[5] + wb[7];  break;
            default: v = wb[8];          break;
        }
        wcs[l * 16 + j * 7 + r] = v;
    }

    // x slice: 128 channels x 9 float4 (cols clamped; clamped slots are only
    // ever used for masked-out t4 halo values -> garbage-but-finite is fine)
    #pragma unroll
    for (int g = tid; g < 128 * 9; g += NT) {
        int c = g / 9, q = g % 9;
        int col = wbase - 4 + q * 4;
        col = col < 0 ? 0 : (col > 52 ? 52 : col);
        float4 v = *(const float4*)(x + c * 3136 + hsrc * 56 + col);
        *(float4*)(xs + c * 36 + q * 4) = v;
    }
    __syncthreads();

    // ---- stage 1: 256 threads -> 8 rows x 32 t4 values ----
    {
        int row  = tid >> 5;          // p*2+j
        int m    = tid & 31;          // local t4 idx, global col = wbase-2+m
        int p    = row >> 1, j = row & 1;
        const float4* wv = (const float4*)(w1s + p * 64);
        const float*  xb = xs + j * 36 + (m + 2);
        float acc = 0.f;
        #pragma unroll
        for (int c4 = 0; c4 < 16; c4++) {
            float4 w4 = wv[c4];
            int c = c4 * 4;           // channel = 2c+j -> xs offset (2c)*36 = c*72
            acc = fmaf(w4.x, xb[(c + 0) * 72], acc);
            acc = fmaf(w4.y, xb[(c + 1) * 72], acc);
            acc = fmaf(w4.z, xb[(c + 2) * 72], acc);
            acc = fmaf(w4.w, xb[(c + 3) * 72], acc);
        }
        t4s[row * 33 + m] = acc;
    }
    __syncthreads();

    // ---- stage 2: thread = (c_out, half) -> 14 outputs ----
    const int c_out = tid >> 1;
    const int qq    = tid & 1;
    const int l     = c_out >> 2, p = c_out & 3;
    const int nbase = wbase + qq * 14;        // global n of first output

    float T0[18], T1[18];
    {
        const float* tb0 = t4s + (p * 2) * 33 + qq * 14;
        const float* tb1 = tb0 + 33;
        #pragma unroll
        for (int u = 0; u < 18; u++) {
            int gc = nbase - 2 + u;           // global t4 column
            bool ok = (gc >= 0) & (gc <= 55);
            T0[u] = ok ? tb0[u] : 0.f;
            T1[u] = ok ? tb1[u] : 0.f;
        }
    }

    const float4* wp = (const float4*)(wcs + l * 16);
    float4 A = wp[0];   // j0: r0 r1 r2 r3
    float4 B = wp[1];   // j0: r4 r5 r6 | j1: r0
    float4 C = wp[2];   // j1: r1 r2 r3 r4
    float4 D = wp[3];   // j1: r5 r6 - -
    float wc0 = A.z + A.w + B.x;              // j0 center
    float wc1 = C.y + C.z + C.w;              // j1 center

    float obuf[14];
    #pragma unroll
    for (int i = 0; i < 14; i++) {
        float acc;
        acc  = fmaf(A.x, T0[i],     0.f);
        acc  = fmaf(A.y, T0[i + 1], acc);
        acc  = fmaf(wc0, T0[i + 2], acc);
        acc  = fmaf(B.y, T0[i + 3], acc);
        acc  = fmaf(B.z, T0[i + 4], acc);
        acc  = fmaf(B.w, T1[i],     acc);
        acc  = fmaf(C.x, T1[i + 1], acc);
        acc  = fmaf(wc1, T1[i + 2], acc);
        acc  = fmaf(D.x, T1[i + 3], acc);
        acc  = fmaf(D.y, T1[i + 4], acc);
        obuf[i] = acc;
    }
    // edge fixups: n=0 drops r3 from center, n=55 drops r4
    if (nbase == 0)  obuf[0]  -= A.w * T0[2]  + C.z * T1[2];
    if (nbase == 42) obuf[13] -= B.x * T0[15] + C.w * T1[15];

    float* ob = out + c_out * 3136 + o * 56 + nbase;
    #pragma unroll
    for (int k = 0; k < 7; k++)
        *(float2*)(ob + 2 * k) = make_float2(obuf[2 * k], obuf[2 * k + 1]);
}

extern "C" void kernel_launch(void* const* d_in, const int* in_sizes, int n_in,
                              void* d_out, int out_size) {
    const float* x  = (const float*)d_in[0];
    const float* w0 = (const float*)d_in[1];
    const float* w1 = (const float*)d_in[2];
    float* out = (float*)d_out;
    fused_shuffleconv2<<<112, NT>>>(x, w0, w1, out);
}